// round 2
// baseline (speedup 1.0000x reference)
#include <cuda_runtime.h>
#include <math.h>
#include <stdint.h>

// ---------------- problem constants ----------------
#define B_ 2048
#define D_ 512
#define C_ 50000
#define NPAD_ 50048      // 391 * 128, zero-padded class rows

__device__ __constant__ float kCOS_M = 0.86602540378443864676f; // cos(pi/6)
__device__ __constant__ float kSIN_M = 0.5f;                    // sin(pi/6)
__device__ __constant__ float kTH    = -0.86602540378443864676f;// cos(pi - m)
__device__ __constant__ float kMM    = 0.26179938779914943654f; // sin(pi-m)*m
#define S_SCALE 15.0f
#define EPS_ 1e-12f

// ---------------- scratch (static device globals; no allocation) ----------------
__device__ float g_xn[B_ * D_];          // 4 MB   normalized x
__device__ float g_wn[NPAD_ * D_];       // 102.5 MB normalized + padded W
__device__ float g_rowloss[B_];
__device__ int   g_label[B_];
__device__ int   g_is64;

// ---------------- label dtype probe ----------------
// If labels are int64 (little-endian, values < 2^32), every odd 32-bit word of
// the first 8 KB is 0. If int32, those words are real labels (~never all zero).
__global__ void detect_label_kernel(const int* lab32) {
    __shared__ int red[256];
    int acc = 0;
    for (int i = 2 * threadIdx.x + 1; i < 2048; i += 512) acc |= lab32[i];
    red[threadIdx.x] = acc;
    __syncthreads();
    for (int s = 128; s > 0; s >>= 1) {
        if (threadIdx.x < s) red[threadIdx.x] |= red[threadIdx.x + s];
        __syncthreads();
    }
    if (threadIdx.x == 0) g_is64 = (red[0] == 0) ? 1 : 0;
}

__global__ void extract_label_kernel(const void* lab) {
    int i = blockIdx.x * blockDim.x + threadIdx.x;
    if (i >= B_) return;
    if (g_is64) g_label[i] = (int)((const long long*)lab)[i];
    else        g_label[i] = ((const int*)lab)[i];
}

// ---------------- row L2 normalize (one block per row, 128 threads, float4) ----
__global__ void norm_x_kernel(const float* __restrict__ x) {
    int row = blockIdx.x;
    int t = threadIdx.x;
    float4 v = ((const float4*)(x + (size_t)row * D_))[t];
    float ss = v.x * v.x + v.y * v.y + v.z * v.z + v.w * v.w;
    #pragma unroll
    for (int o = 16; o > 0; o >>= 1) ss += __shfl_xor_sync(0xffffffffu, ss, o);
    __shared__ float ws[4];
    if ((t & 31) == 0) ws[t >> 5] = ss;
    __syncthreads();
    float inv = 1.0f / fmaxf(sqrtf(ws[0] + ws[1] + ws[2] + ws[3]), EPS_);
    v.x *= inv; v.y *= inv; v.z *= inv; v.w *= inv;
    ((float4*)(g_xn + (size_t)row * D_))[t] = v;
}

__global__ void norm_w_kernel(const float* __restrict__ w) {
    int row = blockIdx.x;
    int t = threadIdx.x;
    if (row >= C_) {   // zero padding rows
        float4 z = make_float4(0.f, 0.f, 0.f, 0.f);
        ((float4*)(g_wn + (size_t)row * D_))[t] = z;
        return;
    }
    float4 v = ((const float4*)(w + (size_t)row * D_))[t];
    float ss = v.x * v.x + v.y * v.y + v.z * v.z + v.w * v.w;
    #pragma unroll
    for (int o = 16; o > 0; o >>= 1) ss += __shfl_xor_sync(0xffffffffu, ss, o);
    __shared__ float ws[4];
    if ((t & 31) == 0) ws[t >> 5] = ss;
    __syncthreads();
    float inv = 1.0f / fmaxf(sqrtf(ws[0] + ws[1] + ws[2] + ws[3]), EPS_);
    v.x *= inv; v.y *= inv; v.z *= inv; v.w *= inv;
    ((float4*)(g_wn + (size_t)row * D_))[t] = v;
}

// ---------------- GEMM 128x128x16 tiles, 256 threads, 8x8 per thread --------
// out[m, n] = S * margin( xn[m,:] . wn[n,:] )
#define BM 128
#define BN 128
#define BK 16
#define LDT 132   // smem row padding to break kq-group bank conflicts

__global__ void __launch_bounds__(256) gemm_margin_kernel(float* __restrict__ out) {
    __shared__ float As[BK][LDT];
    __shared__ float Bs[BK][LDT];

    const int tid = threadIdx.x;
    const int n0 = blockIdx.x * BN;
    const int m0 = blockIdx.y * BM;
    const int tx = tid & 15;
    const int ty = tid >> 4;

    float acc[8][8];
    #pragma unroll
    for (int i = 0; i < 8; i++)
        #pragma unroll
        for (int j = 0; j < 8; j++) acc[i][j] = 0.f;

    for (int k0 = 0; k0 < D_; k0 += BK) {
        #pragma unroll
        for (int half = 0; half < 2; half++) {
            int idx = tid + 256 * half;
            int row = idx >> 2;       // 0..127
            int kq  = idx & 3;        // which float4 along K
            float4 a = *(const float4*)(&g_xn[(size_t)(m0 + row) * D_ + k0 + kq * 4]);
            As[kq * 4 + 0][row] = a.x;
            As[kq * 4 + 1][row] = a.y;
            As[kq * 4 + 2][row] = a.z;
            As[kq * 4 + 3][row] = a.w;
            float4 b = *(const float4*)(&g_wn[(size_t)(n0 + row) * D_ + k0 + kq * 4]);
            Bs[kq * 4 + 0][row] = b.x;
            Bs[kq * 4 + 1][row] = b.y;
            Bs[kq * 4 + 2][row] = b.z;
            Bs[kq * 4 + 3][row] = b.w;
        }
        __syncthreads();

        #pragma unroll
        for (int k = 0; k < BK; k++) {
            float a[8], b[8];
            *(float4*)(a)     = *(const float4*)(&As[k][ty * 8]);
            *(float4*)(a + 4) = *(const float4*)(&As[k][ty * 8 + 4]);
            *(float4*)(b)     = *(const float4*)(&Bs[k][tx * 8]);
            *(float4*)(b + 4) = *(const float4*)(&Bs[k][tx * 8 + 4]);
            #pragma unroll
            for (int i = 0; i < 8; i++)
                #pragma unroll
                for (int j = 0; j < 8; j++) acc[i][j] = fmaf(a[i], b[j], acc[i][j]);
        }
        __syncthreads();
    }

    // epilogue: ArcFace margin on target class, scale by S, guarded store
    int lab[8];
    #pragma unroll
    for (int i = 0; i < 8; i++) lab[i] = g_label[m0 + ty * 8 + i];

    #pragma unroll
    for (int i = 0; i < 8; i++) {
        int row = m0 + ty * 8 + i;
        #pragma unroll
        for (int j = 0; j < 8; j++) {
            int col = n0 + tx * 8 + j;
            if (col < C_) {
                float c = acc[i][j];
                float o = c;
                if (col == lab[i]) {
                    float sin_t = sqrtf(fmaxf(1.f - c * c, 0.f));
                    float phi = c * kCOS_M - sin_t * kSIN_M;
                    o = (c - kTH > 0.f) ? phi : (c - kMM);
                }
                out[(size_t)row * C_ + col] = S_SCALE * o;
            }
        }
    }
}

// ---------------- online log-sum-exp per row + per-row loss contribution ----
__global__ void row_lse_kernel(const float* __restrict__ out) {
    const int r = blockIdx.x;
    const int t = threadIdx.x;
    const float* o = out + (size_t)r * C_;

    float m = -1e30f, s = 0.f;
    for (int c = t; c < C_; c += 256) {
        float v = o[c];
        if (v > m) { s = s * __expf(m - v) + 1.f; m = v; }
        else       { s += __expf(v - m); }
    }
    __shared__ float sm_[256], ss_[256];
    sm_[t] = m; ss_[t] = s;
    __syncthreads();
    for (int str = 128; str > 0; str >>= 1) {
        if (t < str) {
            float m2 = sm_[t + str], s2 = ss_[t + str];
            float mm = fmaxf(sm_[t], m2);
            ss_[t] = ss_[t] * __expf(sm_[t] - mm) + s2 * __expf(m2 - mm);
            sm_[t] = mm;
        }
        __syncthreads();
    }
    if (t == 0) {
        float lse = sm_[0] + logf(ss_[0]);
        g_rowloss[r] = lse - o[g_label[r]];
    }
}

__global__ void finalize_kernel(float* __restrict__ out, int out_size) {
    __shared__ float red[256];
    float a = 0.f;
    for (int i = threadIdx.x; i < B_; i += 256) a += g_rowloss[i];
    red[threadIdx.x] = a;
    __syncthreads();
    for (int s = 128; s > 0; s >>= 1) {
        if (threadIdx.x < s) red[threadIdx.x] += red[threadIdx.x + s];
        __syncthreads();
    }
    if (threadIdx.x == 0) {
        float loss = red[0] / (float)B_;
        // fill every element past the [B,C] logits block (loss scalar slot)
        for (long long i = (long long)B_ * C_; i < (long long)out_size; i++)
            out[i] = loss;
    }
}

// ---------------- launch ----------------
extern "C" void kernel_launch(void* const* d_in, const int* in_sizes, int n_in,
                              void* d_out, int out_size) {
    const float* x   = (const float*)d_in[0];
    const void*  lab = d_in[1];
    const float* w   = (const float*)d_in[2];
    float* out = (float*)d_out;

    detect_label_kernel<<<1, 256>>>((const int*)lab);
    extract_label_kernel<<<(B_ + 255) / 256, 256>>>(lab);
    norm_x_kernel<<<B_, 128>>>(x);
    norm_w_kernel<<<NPAD_, 128>>>(w);

    dim3 grid(NPAD_ / BN, B_ / BM);   // 391 x 16
    gemm_margin_kernel<<<grid, 256>>>(out);

    row_lse_kernel<<<B_, 256>>>(out);
    finalize_kernel<<<1, 256>>>(out, out_size);
}

// round 4
// speedup vs baseline: 2.0188x; 2.0188x over previous
#include <cuda_runtime.h>
#include <cuda_bf16.h>
#include <math.h>
#include <stdint.h>

// ---------------- problem constants ----------------
#define B_ 2048
#define D_ 512
#define C_ 50000
#define NPAD_ 50048      // 391 * 128, zero-padded class rows

__device__ __constant__ float kCOS_M = 0.86602540378443864676f; // cos(pi/6)
__device__ __constant__ float kSIN_M = 0.5f;                    // sin(pi/6)
__device__ __constant__ float kTH    = -0.86602540378443864676f;// cos(pi - m)
__device__ __constant__ float kMM    = 0.26179938779914943654f; // sin(pi-m)*m
#define S_SCALE 15.0f
#define EPS_ 1e-12f

// ---------------- scratch (static device globals; no allocation) ------------
__device__ __align__(128) __nv_bfloat16 g_xh[B_ * D_];      // 2 MB
__device__ __align__(128) __nv_bfloat16 g_xl[B_ * D_];      // 2 MB
__device__ __align__(128) __nv_bfloat16 g_wh[NPAD_ * D_];   // 51.25 MB
__device__ __align__(128) __nv_bfloat16 g_wl[NPAD_ * D_];   // 51.25 MB
__device__ float g_rowloss[B_];
__device__ int   g_label[B_];
__device__ int   g_is64;

// ---------------- helpers ----------------
__device__ __forceinline__ uint32_t smem_u32(const void* p) {
    return (uint32_t)__cvta_generic_to_shared(p);
}
__device__ __forceinline__ void cp16(uint32_t dst, const void* src) {
    asm volatile("cp.async.cg.shared.global [%0], [%1], 16;"
                 :: "r"(dst), "l"(__cvta_generic_to_global(src)));
}
#define CP_COMMIT() asm volatile("cp.async.commit_group;" ::: "memory")
#define CP_WAIT1()  asm volatile("cp.async.wait_group 1;" ::: "memory")
#define CP_WAIT0()  asm volatile("cp.async.wait_group 0;" ::: "memory")

__device__ __forceinline__ void ldm4(uint32_t r[4], uint32_t addr) {
    asm volatile("ldmatrix.sync.aligned.m8n8.x4.shared.b16 {%0,%1,%2,%3}, [%4];"
                 : "=r"(r[0]), "=r"(r[1]), "=r"(r[2]), "=r"(r[3]) : "r"(addr));
}
__device__ __forceinline__ uint32_t lds32(uint32_t addr) {
    uint32_t v;
    asm volatile("ld.shared.b32 %0, [%1];" : "=r"(v) : "r"(addr));
    return v;
}
__device__ __forceinline__ void mma16816(float c[4], const uint32_t a[4],
                                         uint32_t b0, uint32_t b1) {
    asm volatile(
        "mma.sync.aligned.m16n8k16.row.col.f32.bf16.bf16.f32 "
        "{%0,%1,%2,%3}, {%4,%5,%6,%7}, {%8,%9}, {%0,%1,%2,%3};"
        : "+f"(c[0]), "+f"(c[1]), "+f"(c[2]), "+f"(c[3])
        : "r"(a[0]), "r"(a[1]), "r"(a[2]), "r"(a[3]), "r"(b0), "r"(b1));
}

// ---------------- label dtype probe ----------------
__global__ void detect_label_kernel(const int* lab32) {
    __shared__ int red[256];
    int acc = 0;
    for (int i = 2 * threadIdx.x + 1; i < 2048; i += 512) acc |= lab32[i];
    red[threadIdx.x] = acc;
    __syncthreads();
    for (int s = 128; s > 0; s >>= 1) {
        if (threadIdx.x < s) red[threadIdx.x] |= red[threadIdx.x + s];
        __syncthreads();
    }
    if (threadIdx.x == 0) g_is64 = (red[0] == 0) ? 1 : 0;
}

__global__ void extract_label_kernel(const void* lab) {
    int i = blockIdx.x * blockDim.x + threadIdx.x;
    if (i >= B_) return;
    if (g_is64) g_label[i] = (int)((const long long*)lab)[i];
    else        g_label[i] = ((const int*)lab)[i];
}

// ---------------- normalize + bf16 hi/lo split ----------------
__device__ __forceinline__ uint32_t pack_bf2(__nv_bfloat16 a, __nv_bfloat16 b) {
    return (uint32_t)__bfloat16_as_ushort(a) | ((uint32_t)__bfloat16_as_ushort(b) << 16);
}

__device__ __forceinline__ void split_store(__nv_bfloat16* hi_arr, __nv_bfloat16* lo_arr,
                                            size_t base_elem, int t, float4 v) {
    __nv_bfloat16 h0 = __float2bfloat16_rn(v.x);
    __nv_bfloat16 h1 = __float2bfloat16_rn(v.y);
    __nv_bfloat16 h2 = __float2bfloat16_rn(v.z);
    __nv_bfloat16 h3 = __float2bfloat16_rn(v.w);
    __nv_bfloat16 l0 = __float2bfloat16_rn(v.x - __bfloat162float(h0));
    __nv_bfloat16 l1 = __float2bfloat16_rn(v.y - __bfloat162float(h1));
    __nv_bfloat16 l2 = __float2bfloat16_rn(v.z - __bfloat162float(h2));
    __nv_bfloat16 l3 = __float2bfloat16_rn(v.w - __bfloat162float(h3));
    uint2 hp = make_uint2(pack_bf2(h0, h1), pack_bf2(h2, h3));
    uint2 lp = make_uint2(pack_bf2(l0, l1), pack_bf2(l2, l3));
    ((uint2*)(hi_arr + base_elem))[t] = hp;
    ((uint2*)(lo_arr + base_elem))[t] = lp;
}

__global__ void norm_x_kernel(const float* __restrict__ x) {
    int row = blockIdx.x;
    int t = threadIdx.x;
    float4 v = ((const float4*)(x + (size_t)row * D_))[t];
    float ss = v.x * v.x + v.y * v.y + v.z * v.z + v.w * v.w;
    #pragma unroll
    for (int o = 16; o > 0; o >>= 1) ss += __shfl_xor_sync(0xffffffffu, ss, o);
    __shared__ float ws[4];
    if ((t & 31) == 0) ws[t >> 5] = ss;
    __syncthreads();
    float inv = 1.0f / fmaxf(sqrtf(ws[0] + ws[1] + ws[2] + ws[3]), EPS_);
    v.x *= inv; v.y *= inv; v.z *= inv; v.w *= inv;
    split_store(g_xh, g_xl, (size_t)row * D_, t, v);
}

__global__ void norm_w_kernel(const float* __restrict__ w) {
    int row = blockIdx.x;
    int t = threadIdx.x;
    if (row >= C_) {
        uint2 z = make_uint2(0u, 0u);
        ((uint2*)(g_wh + (size_t)row * D_))[t] = z;
        ((uint2*)(g_wl + (size_t)row * D_))[t] = z;
        return;
    }
    float4 v = ((const float4*)(w + (size_t)row * D_))[t];
    float ss = v.x * v.x + v.y * v.y + v.z * v.z + v.w * v.w;
    #pragma unroll
    for (int o = 16; o > 0; o >>= 1) ss += __shfl_xor_sync(0xffffffffu, ss, o);
    __shared__ float ws[4];
    if ((t & 31) == 0) ws[t >> 5] = ss;
    __syncthreads();
    float inv = 1.0f / fmaxf(sqrtf(ws[0] + ws[1] + ws[2] + ws[3]), EPS_);
    v.x *= inv; v.y *= inv; v.z *= inv; v.w *= inv;
    split_store(g_wh, g_wl, (size_t)row * D_, t, v);
}

// ---------------- mma.sync GEMM + margin epilogue ----------------
// CTA tile 128x128, 8 warps each 64x32, BK=64, SW128 swizzle, 2-stage cp.async.
// Stage layout: Ah[16K] Al[16K] Bh[16K] Bl[16K] = 64KB. 2 stages = 128KB.
#define STAGE_BYTES 65536
#define MAT_BYTES   16384
#define GEMM_SMEM   (2 * STAGE_BYTES)

__global__ void __launch_bounds__(256, 1) gemm_mma_kernel(float* __restrict__ out) {
    extern __shared__ __align__(1024) char smem[];
    const uint32_t sb = smem_u32(smem);
    const int tid  = threadIdx.x;
    const int lane = tid & 31;
    const int w    = tid >> 5;
    const int wm   = w & 1;        // 2 warp-rows  (64 m each)
    const int wn   = w >> 1;       // 4 warp-cols  (32 n each)
    const int m0   = blockIdx.x * 128;   // m inner -> B tiles shared via L2
    const int n0   = blockIdx.y * 128;

    // ---- cp.async addressing: thread t loads row t>>1, chunks (t&1)*4 .. +3
    const int lrow = tid >> 1;
    const int half = tid & 1;
    const uint32_t rowoff = (uint32_t)lrow * 128u;
    const int rsw = lrow & 7;
    const __nv_bfloat16* gAh = g_xh + (size_t)(m0 + lrow) * D_ + half * 32;
    const __nv_bfloat16* gAl = g_xl + (size_t)(m0 + lrow) * D_ + half * 32;
    const __nv_bfloat16* gBh = g_wh + (size_t)(n0 + lrow) * D_ + half * 32;
    const __nv_bfloat16* gBl = g_wl + (size_t)(n0 + lrow) * D_ + half * 32;

    float acc[4][4][4];
    #pragma unroll
    for (int i = 0; i < 4; i++)
        #pragma unroll
        for (int j = 0; j < 4; j++)
            #pragma unroll
            for (int q = 0; q < 4; q++) acc[i][j][q] = 0.f;

    // ---- fragment addressing (constant per thread)
    const int rowA   = wm * 64 + (lane & 15);
    const int axor   = rowA & 7;
    const int laneHi = lane >> 4;
    const int nB     = wn * 32 + (lane >> 2);
    const int nxor   = nB & 7;
    const uint32_t lo4 = (lane & 3) * 4;

#define LOAD_STAGE(s, ki) do {                                                  \
    uint32_t st_ = sb + (s) * STAGE_BYTES;                                      \
    int kc_ = (ki) * 64;                                                        \
    _Pragma("unroll")                                                           \
    for (int c_ = 0; c_ < 4; c_++) {                                            \
        int chunk_ = half * 4 + c_;                                             \
        uint32_t o_ = rowoff + (uint32_t)((chunk_ ^ rsw) << 4);                 \
        cp16(st_ + o_,                 gAh + kc_ + c_ * 8);                     \
        cp16(st_ + MAT_BYTES + o_,     gAl + kc_ + c_ * 8);                     \
        cp16(st_ + 2 * MAT_BYTES + o_, gBh + kc_ + c_ * 8);                     \
        cp16(st_ + 3 * MAT_BYTES + o_, gBl + kc_ + c_ * 8);                     \
    }                                                                           \
} while (0)

    LOAD_STAGE(0, 0);
    CP_COMMIT();

    for (int ki = 0; ki < 8; ki++) {
        if (ki < 7) {
            LOAD_STAGE((ki + 1) & 1, ki + 1);
            CP_COMMIT();
            CP_WAIT1();
        } else {
            CP_WAIT0();
        }
        __syncthreads();

        const uint32_t st = sb + (ki & 1) * STAGE_BYTES;
        const uint32_t aBaseH = st + (uint32_t)rowA * 128u;
        const uint32_t aBaseL = aBaseH + MAT_BYTES;
        const uint32_t bBaseH = st + 2 * MAT_BYTES + (uint32_t)nB * 128u;
        const uint32_t bBaseL = bBaseH + MAT_BYTES;

        #pragma unroll
        for (int kk = 0; kk < 4; kk++) {
            uint32_t ah[4][4], al[4][4];
            #pragma unroll
            for (int i = 0; i < 4; i++) {
                uint32_t so = (uint32_t)(((kk * 2 + laneHi) ^ axor) << 4);
                ldm4(ah[i], aBaseH + i * 2048 + so);
                ldm4(al[i], aBaseL + i * 2048 + so);
            }
            uint32_t bh[4][2], bl[4][2];
            const uint32_t s0 = (uint32_t)(((kk * 2)     ^ nxor) << 4) + lo4;
            const uint32_t s1 = (uint32_t)(((kk * 2 + 1) ^ nxor) << 4) + lo4;
            #pragma unroll
            for (int j = 0; j < 4; j++) {
                bh[j][0] = lds32(bBaseH + j * 1024 + s0);
                bh[j][1] = lds32(bBaseH + j * 1024 + s1);
                bl[j][0] = lds32(bBaseL + j * 1024 + s0);
                bl[j][1] = lds32(bBaseL + j * 1024 + s1);
            }
            #pragma unroll
            for (int i = 0; i < 4; i++)
                #pragma unroll
                for (int j = 0; j < 4; j++) {
                    mma16816(acc[i][j], ah[i], bh[j][0], bh[j][1]);
                    mma16816(acc[i][j], al[i], bh[j][0], bh[j][1]);
                    mma16816(acc[i][j], ah[i], bl[j][0], bl[j][1]);
                }
        }
        __syncthreads();
    }

    // ---- epilogue: margin on target class, scale, streaming store
    #pragma unroll
    for (int i = 0; i < 4; i++) {
        const int r0 = m0 + wm * 64 + i * 16 + (lane >> 2);
        const int r1 = r0 + 8;
        const int lab0 = g_label[r0];
        const int lab1 = g_label[r1];
        float* const o0 = out + (size_t)r0 * C_;
        float* const o1 = out + (size_t)r1 * C_;
        #pragma unroll
        for (int j = 0; j < 4; j++) {
            const int col = n0 + wn * 32 + j * 8 + (lane & 3) * 2;
            if (col < C_) {
                float2 v0, v1;
                float* p0 = (float*)&v0;
                float* p1 = (float*)&v1;
                #pragma unroll
                for (int q = 0; q < 2; q++) {
                    float c = acc[i][j][q];
                    if (col + q == lab0) {
                        float st2 = sqrtf(fmaxf(1.f - c * c, 0.f));
                        float phi = c * kCOS_M - st2 * kSIN_M;
                        c = (c - kTH > 0.f) ? phi : (c - kMM);
                    }
                    p0[q] = S_SCALE * c;
                    float d = acc[i][j][q + 2];
                    if (col + q == lab1) {
                        float st2 = sqrtf(fmaxf(1.f - d * d, 0.f));
                        float phi = d * kCOS_M - st2 * kSIN_M;
                        d = (d - kTH > 0.f) ? phi : (d - kMM);
                    }
                    p1[q] = S_SCALE * d;
                }
                __stcs(reinterpret_cast<float2*>(o0 + col), v0);
                __stcs(reinterpret_cast<float2*>(o1 + col), v1);
            }
        }
    }
}

// ---------------- online log-sum-exp per row + loss ----------------
__global__ void row_lse_kernel(const float* __restrict__ out) {
    const int r = blockIdx.x;
    const int t = threadIdx.x;
    const float* o = out + (size_t)r * C_;

    float m = -1e30f, s = 0.f;
    for (int c = t; c < C_; c += 256) {
        float v = __ldcs(o + c);
        if (v > m) { s = s * __expf(m - v) + 1.f; m = v; }
        else       { s += __expf(v - m); }
    }
    __shared__ float sm_[256], ss_[256];
    sm_[t] = m; ss_[t] = s;
    __syncthreads();
    for (int str = 128; str > 0; str >>= 1) {
        if (t < str) {
            float m2 = sm_[t + str], s2 = ss_[t + str];
            float mm = fmaxf(sm_[t], m2);
            ss_[t] = ss_[t] * __expf(sm_[t] - mm) + s2 * __expf(m2 - mm);
            sm_[t] = mm;
        }
        __syncthreads();
    }
    if (t == 0) {
        float lse = sm_[0] + logf(ss_[0]);
        g_rowloss[r] = lse - o[g_label[r]];
    }
}

__global__ void finalize_kernel(float* __restrict__ out, int out_size) {
    __shared__ float red[256];
    float a = 0.f;
    for (int i = threadIdx.x; i < B_; i += 256) a += g_rowloss[i];
    red[threadIdx.x] = a;
    __syncthreads();
    for (int s = 128; s > 0; s >>= 1) {
        if (threadIdx.x < s) red[threadIdx.x] += red[threadIdx.x + s];
        __syncthreads();
    }
    if (threadIdx.x == 0) {
        float loss = red[0] / (float)B_;
        for (long long i = (long long)B_ * C_; i < (long long)out_size; i++)
            out[i] = loss;
    }
}

// ---------------- launch ----------------
extern "C" void kernel_launch(void* const* d_in, const int* in_sizes, int n_in,
                              void* d_out, int out_size) {
    const float* x   = (const float*)d_in[0];
    const void*  lab = d_in[1];
    const float* w   = (const float*)d_in[2];
    float* out = (float*)d_out;

    cudaFuncSetAttribute(gemm_mma_kernel,
                         cudaFuncAttributeMaxDynamicSharedMemorySize, GEMM_SMEM);

    detect_label_kernel<<<1, 256>>>((const int*)lab);
    extract_label_kernel<<<(B_ + 255) / 256, 256>>>(lab);
    norm_x_kernel<<<B_, 128>>>(x);
    norm_w_kernel<<<NPAD_, 128>>>(w);

    dim3 grid(B_ / 128, NPAD_ / 128);   // (16, 391), m inner
    gemm_mma_kernel<<<grid, 256, GEMM_SMEM>>>(out);

    row_lse_kernel<<<B_, 256>>>(out);
    finalize_kernel<<<1, 256>>>(out, out_size);
}